// round 7
// baseline (speedup 1.0000x reference)
#include <cuda_runtime.h>
#include <cstdint>

#define BB 4
#define TT 256
#define LL 216
#define EPC 12
#define EROOT 12
#define EQUAL 16
#define KK 41
#define W_NM 0.1f
#define W_ADV 0.001f

// device scratch (no cudaMalloc allowed)
__device__ __align__(16) float g_yhi[BB][TT][LL];      // y[τ,l] = x[τ,:]·h[:,l], hi
__device__ __align__(16) float g_ylo[BB][TT][LL];      // compensation of the dot
__device__ __align__(16) float g_Dhi[BB][TT + 1][LL];  // D = prefix(y), compensated hi
__device__ __align__(16) float g_Dlo[BB][TT + 1][LL];  // compensation (lo) part

// ---------------- K0: y[τ,l] = x[τ,:]·h[:,l] with compensated dot ----------------
// grid (64 t-chunks, BB), 216 threads; thread = one l-column, 4 τ-rows per CTA
__global__ __launch_bounds__(216)
void y_kernel(const float* __restrict__ apc,
              const float* __restrict__ aroot,
              const float* __restrict__ aqual,
              const float* __restrict__ iroot,
              const float* __restrict__ iqual,
              const float* __restrict__ hpc,
              const float* __restrict__ hroot,
              const float* __restrict__ hqual,
              const int* __restrict__ pc_only) {
    __shared__ float xs[4][KK];
    const int t0 = blockIdx.x * 4;
    const int b  = blockIdx.y;
    const int l  = threadIdx.x;

    // stage x rows: x[τ,k] (k<12: pc; 12..23: root-adv; 24..39: qual-adv; 40: 1)
    for (int idx = l; idx < 4 * KK; idx += 216) {
        int tt = idx / KK, k = idx - tt * KK;
        int t = t0 + tt;
        float x;
        if (k < 12) {
            x = apc[(b * TT + t) * EPC + k];
        } else if (k < 24) {
            int j = k - 12;
            x = aroot[(b * TT + t) * EROOT + j] - W_ADV * iroot[(b * TT + t) * EROOT + j];
        } else if (k < 40) {
            int j = k - 24;
            x = aqual[(b * TT + t) * EQUAL + j] - W_ADV * iqual[(b * TT + t) * EQUAL + j];
        } else {
            x = 1.0f;  // channel 40 carries the -W_NM*Hs term (segment mean == 1)
        }
        xs[tt][k] = x;
    }

    // fold h for this l (recomputed per CTA; inputs hot in L2)
    int po = pc_only ? pc_only[0] : 0;
    float h[KK];
    {
        float hs = 0.0f;
        #pragma unroll
        for (int j = 0; j < 12; j++) { h[j] = hpc[(b * LL + l) * EPC + j]; hs += h[j]; }
        float coef = (1.0f + 2.0f * W_NM) - W_ADV / hs;
        #pragma unroll
        for (int j = 0; j < 12; j++) h[j] = h[j] * coef - W_NM;
        #pragma unroll
        for (int j = 0; j < 12; j++) h[12 + j] = po ? 0.0f : hroot[(b * LL + l) * EROOT + j];
        #pragma unroll
        for (int j = 0; j < 16; j++) h[24 + j] = po ? 0.0f : hqual[(b * LL + l) * EQUAL + j];
        h[40] = -W_NM * hs;
    }
    __syncthreads();

    #pragma unroll
    for (int tt = 0; tt < 4; tt++) {
        float s = 0.0f, c = 0.0f;
        #pragma unroll
        for (int k = 0; k < KK; k++) {
            float a  = xs[tt][k];
            float p  = a * h[k];
            float ep = fmaf(a, h[k], -p);   // exact product error
            float t2 = s + p;               // TwoSum
            float z  = t2 - s;
            float e2 = (s - (t2 - z)) + (p - z);
            s = t2;
            c += ep + e2;
        }
        g_yhi[b][t0 + tt][l] = s;
        g_ylo[b][t0 + tt][l] = c;
    }
}

// ---------------- K1: compensated prefix scan over τ -> Dhi/Dlo ----------------
// grid BB, 216 threads; thread = one l-column, sequential 256-step TwoSum chain
__global__ __launch_bounds__(216)
void scan_kernel() {
    const int b = blockIdx.x;
    const int l = threadIdx.x;
    float s = 0.0f, c = 0.0f;
    g_Dhi[b][0][l] = 0.0f;
    g_Dlo[b][0][l] = 0.0f;
    #pragma unroll 4
    for (int t = 0; t < TT; t++) {
        float p  = g_yhi[b][t][l];
        float t2 = s + p;                   // TwoSum
        float z  = t2 - s;
        float e  = (s - (t2 - z)) + (p - z);
        s = t2;
        c += e + g_ylo[b][t][l];
        g_Dhi[b][t + 1][l] = s;
        g_Dlo[b][t + 1][l] = c;
    }
}

// ---------------- main: out[b,s,e,l] = (D[e+1,l]-D[s,l]) * inv_len, store-bound ----------------
// tile = 8 s x 32 e x full L; 256 threads; thread: chunk c=tid&63 (c<54 active), e-group g=tid>>6
// grid: x = st (32) fastest so consecutive CTAs share the 32 staged E-rows in L2
// smem floats: hiS[8*216] | loS[8*216] | hiE[32*216] | loE[32*216] | inv[256]
#define SM_LOS 1728
#define SM_HIE 3456
#define SM_LOE 10368
#define SM_INV 17280
#define SM_FLOATS 17536   // 70144 bytes

__global__ __launch_bounds__(256, 2)
void main_kernel(float* __restrict__ out) {
    extern __shared__ float sm[];
    const int tid = threadIdx.x;
    const int st = blockIdx.x, et = blockIdx.y, b = blockIdx.z;
    const int s0 = st * 8, e0 = et * 32;

    const float* __restrict__ Dhi = &g_Dhi[b][0][0];
    const float* __restrict__ Dlo = &g_Dlo[b][0][0];

    // stage 40 D-rows (8 s-rows, 32 e-rows at t=e+1) as hi/lo
    for (int idx = tid; idx < 40 * 54; idx += 256) {
        int row = idx / 54, c = idx - row * 54;
        int t = (row < 8) ? (s0 + row) : (e0 + (row - 8) + 1);
        float4 vh = *(const float4*)(Dhi + t * LL + c * 4);
        float4 vl = *(const float4*)(Dlo + t * LL + c * 4);
        int dh = (row < 8) ? (row * LL) : (SM_HIE + (row - 8) * LL);
        int dl = dh + ((row < 8) ? SM_LOS : (SM_LOE - SM_HIE));
        *(float4*)(sm + dh + c * 4) = vh;
        *(float4*)(sm + dl + c * 4) = vl;
    }
    // inv table with validity baked in (inv = 0 for e < s)
    {
        int s = tid >> 5, e = tid & 31;
        int len = (e0 + e) - (s0 + s) + 1;
        sm[SM_INV + tid] = (len >= 1) ? __fdividef(1.0f, (float)len) : 0.0f;
    }
    __syncthreads();

    const int c = tid & 63;
    const int g = tid >> 6;
    if (c >= 54) return;

    const float4* __restrict__ hiS4 = (const float4*)sm;
    const float4* __restrict__ loS4 = (const float4*)(sm + SM_LOS);
    const float4* __restrict__ hiE4 = (const float4*)(sm + SM_HIE);
    const float4* __restrict__ loE4 = (const float4*)(sm + SM_LOE);
    const float*  __restrict__ invt = sm + SM_INV;

    float* base = out + ((size_t)(b * 65536 + s0 * 256 + e0 + g * 8)) * LL + c * 4;

    #pragma unroll 1
    for (int s = 0; s < 8; s++) {
        float4 hs = hiS4[s * 54 + c];
        float4 ls = loS4[s * 54 + c];
        float* ps = base + (size_t)s * (256 * LL);
        #pragma unroll
        for (int eg = 0; eg < 8; eg++) {
            int e = g * 8 + eg;
            float inv = invt[s * 32 + e];
            float4 he = hiE4[e * 54 + c];
            float4 le = loE4[e * 54 + c];
            float4 v;
            v.x = ((he.x - hs.x) + (le.x - ls.x)) * inv;
            v.y = ((he.y - hs.y) + (le.y - ls.y)) * inv;
            v.z = ((he.z - hs.z) + (le.z - ls.z)) * inv;
            v.w = ((he.w - hs.w) + (le.w - ls.w)) * inv;
            __stcs((float4*)(ps + eg * LL), v);   // streaming store: write-once output
        }
    }
}

extern "C" void kernel_launch(void* const* d_in, const int* in_sizes, int n_in,
                              void* d_out, int out_size) {
    const float* apc   = (const float*)d_in[0];
    const float* aroot = (const float*)d_in[1];
    const float* aqual = (const float*)d_in[2];
    // d_in[3] = inactive_pc: unused by the reference
    const float* iroot = (const float*)d_in[4];
    const float* iqual = (const float*)d_in[5];
    const float* hpc   = (const float*)d_in[6];
    const float* hroot = (const float*)d_in[7];
    const float* hqual = (const float*)d_in[8];
    const int*   pco   = (n_in > 9) ? (const int*)d_in[9] : nullptr;

    static bool attr_done = false;
    if (!attr_done) {
        cudaFuncSetAttribute(main_kernel, cudaFuncAttributeMaxDynamicSharedMemorySize,
                             SM_FLOATS * 4);
        attr_done = true;
    }

    y_kernel<<<dim3(64, BB), 216>>>(apc, aroot, aqual, iroot, iqual,
                                    hpc, hroot, hqual, pco);
    scan_kernel<<<BB, 216>>>();
    main_kernel<<<dim3(32, 8, BB), 256, SM_FLOATS * 4>>>((float*)d_out);
}

// round 9
// speedup vs baseline: 2.1804x; 2.1804x over previous
#include <cuda_runtime.h>
#include <cstdint>

#define BB 4
#define TT 256
#define LL 216
#define EPC 12
#define EROOT 12
#define EQUAL 16
#define KK 41
#define W_NM 0.1f
#define W_ADV 0.001f

// device scratch (no cudaMalloc allowed)
__device__ float g_cs[BB][TT + 1][48];                 // prefix sums, channel-innermost
__device__ __align__(16) float g_Dhi[BB][TT + 1][LL];  // D = cs @ h, compensated hi
__device__ __align__(16) float g_Dlo[BB][TT + 1][LL];  // compensation (lo) part

// ---------------- K0: prefix scans over t, one (b,channel) per block ----------------
__global__ void prep_kernel(const float* __restrict__ apc,
                            const float* __restrict__ aroot,
                            const float* __restrict__ aqual,
                            const float* __restrict__ iroot,
                            const float* __restrict__ iqual) {
    __shared__ float wsum[8];
    int ch = blockIdx.x % KK;
    int b  = blockIdx.x / KK;
    int t  = threadIdx.x;
    int w  = t >> 5, lane = t & 31;
    float x;
    if (ch < 12) {
        x = apc[(b * TT + t) * EPC + ch];
    } else if (ch < 24) {
        int j = ch - 12;
        x = aroot[(b * TT + t) * EROOT + j] - W_ADV * iroot[(b * TT + t) * EROOT + j];
    } else if (ch < 40) {
        int j = ch - 24;
        x = aqual[(b * TT + t) * EQUAL + j] - W_ADV * iqual[(b * TT + t) * EQUAL + j];
    } else {
        x = 1.0f;  // channel 40 carries the -W_NM*Hs term (segment mean == 1)
    }
    // inclusive warp scan
    float v = x;
    #pragma unroll
    for (int off = 1; off < 32; off <<= 1) {
        float n = __shfl_up_sync(0xFFFFFFFFu, v, off);
        if (lane >= off) v += n;
    }
    if (lane == 31) wsum[w] = v;
    __syncthreads();
    if (t < 8) {
        float s = wsum[t];
        #pragma unroll
        for (int off = 1; off < 8; off <<= 1) {
            float n = __shfl_up_sync(0x000000FFu, s, off);
            if (t >= off) s += n;
        }
        wsum[t] = s;
    }
    __syncthreads();
    float base = (w > 0) ? wsum[w - 1] : 0.0f;
    g_cs[b][t + 1][ch] = v + base;
    if (t == 0) g_cs[b][0][ch] = 0.0f;
}

// ---------------- K1: D = cs @ h, h folded inline, fp32 compensated accumulation ----------------
__global__ __launch_bounds__(224)
void d_kernel(const float* __restrict__ hpc,
              const float* __restrict__ hroot,
              const float* __restrict__ hqual,
              const int* __restrict__ pc_only) {
    __shared__ float cs_s[KK];
    int t = blockIdx.x;   // 0..256
    int b = blockIdx.y;
    int l = threadIdx.x;  // 0..223
    if (l < KK) cs_s[l] = g_cs[b][t][l];
    __syncthreads();
    if (l >= LL) return;

    // fold harmony coefficients for this l (inputs L2-hot; same load count as a g_h read)
    int po = pc_only ? pc_only[0] : 0;
    float h[KK];
    {
        float hs = 0.0f;
        #pragma unroll
        for (int j = 0; j < 12; j++) { h[j] = hpc[(b * LL + l) * EPC + j]; hs += h[j]; }
        float coef = (1.0f + 2.0f * W_NM) - W_ADV / hs;
        #pragma unroll
        for (int j = 0; j < 12; j++) h[j] = h[j] * coef - W_NM;
        #pragma unroll
        for (int j = 0; j < 12; j++) h[12 + j] = po ? 0.0f : hroot[(b * LL + l) * EROOT + j];
        #pragma unroll
        for (int j = 0; j < 16; j++) h[24 + j] = po ? 0.0f : hqual[(b * LL + l) * EQUAL + j];
        h[40] = -W_NM * hs;
    }

    float s = 0.0f, c = 0.0f;
    #pragma unroll
    for (int k = 0; k < KK; k++) {
        float a  = cs_s[k];
        float p  = a * h[k];
        float ep = fmaf(a, h[k], -p);    // exact product error
        float tt = s + p;                // TwoSum
        float z  = tt - s;
        float e2 = (s - (tt - z)) + (p - z);
        s = tt;
        c += ep + e2;
    }
    g_Dhi[b][t][l] = s;
    g_Dlo[b][t][l] = c;
}

// ---------------- main: out[b,s,e,l] = (D[e+1,l]-D[s,l]) * inv_len, store-bound ----------------
// tile = 8 s x 32 e x full L; 256 threads; thread: chunk c=tid&63 (c<54 active), e-group g=tid>>6
// grid: x = st (32) fastest so consecutive CTAs share the 32 staged E-rows in L2
// smem floats: hiS[8*216] | loS[8*216] | hiE[32*216] | loE[32*216] | inv[256]
#define SM_LOS 1728
#define SM_HIE 3456
#define SM_LOE 10368
#define SM_INV 17280
#define SM_FLOATS 17536   // 70144 bytes

__global__ __launch_bounds__(256, 3)
void main_kernel(float* __restrict__ out) {
    extern __shared__ float sm[];
    const int tid = threadIdx.x;
    const int st = blockIdx.x, et = blockIdx.y, b = blockIdx.z;
    const int s0 = st * 8, e0 = et * 32;

    const float* __restrict__ Dhi = &g_Dhi[b][0][0];
    const float* __restrict__ Dlo = &g_Dlo[b][0][0];

    // stage 40 D-rows (8 s-rows, 32 e-rows at t=e+1) as hi/lo
    for (int idx = tid; idx < 40 * 54; idx += 256) {
        int row = idx / 54, c = idx - row * 54;
        int t = (row < 8) ? (s0 + row) : (e0 + (row - 8) + 1);
        float4 vh = *(const float4*)(Dhi + t * LL + c * 4);
        float4 vl = *(const float4*)(Dlo + t * LL + c * 4);
        int dh = (row < 8) ? (row * LL) : (SM_HIE + (row - 8) * LL);
        int dl = dh + ((row < 8) ? SM_LOS : (SM_LOE - SM_HIE));
        *(float4*)(sm + dh + c * 4) = vh;
        *(float4*)(sm + dl + c * 4) = vl;
    }
    // inv table with validity baked in (inv = 0 for e < s)
    {
        int s = tid >> 5, e = tid & 31;
        int len = (e0 + e) - (s0 + s) + 1;
        sm[SM_INV + tid] = (len >= 1) ? __fdividef(1.0f, (float)len) : 0.0f;
    }
    __syncthreads();

    const int c = tid & 63;
    const int g = tid >> 6;
    if (c >= 54) return;

    const float4* __restrict__ hiS4 = (const float4*)sm;
    const float4* __restrict__ loS4 = (const float4*)(sm + SM_LOS);
    const float4* __restrict__ hiE4 = (const float4*)(sm + SM_HIE);
    const float4* __restrict__ loE4 = (const float4*)(sm + SM_LOE);
    const float*  __restrict__ invt = sm + SM_INV;

    float* base = out + ((size_t)(b * 65536 + s0 * 256 + e0 + g * 8)) * LL + c * 4;

    #pragma unroll 1
    for (int s = 0; s < 8; s++) {
        float4 hs = hiS4[s * 54 + c];
        float4 ls = loS4[s * 54 + c];
        float* ps = base + (size_t)s * (256 * LL);
        #pragma unroll
        for (int eg = 0; eg < 8; eg++) {
            int e = g * 8 + eg;
            float inv = invt[s * 32 + e];
            float4 he = hiE4[e * 54 + c];
            float4 le = loE4[e * 54 + c];
            float4 v;
            v.x = ((he.x - hs.x) + (le.x - ls.x)) * inv;
            v.y = ((he.y - hs.y) + (le.y - ls.y)) * inv;
            v.z = ((he.z - hs.z) + (le.z - ls.z)) * inv;
            v.w = ((he.w - hs.w) + (le.w - ls.w)) * inv;
            __stcs((float4*)(ps + eg * LL), v);   // streaming store: write-once output
        }
    }
}

extern "C" void kernel_launch(void* const* d_in, const int* in_sizes, int n_in,
                              void* d_out, int out_size) {
    const float* apc   = (const float*)d_in[0];
    const float* aroot = (const float*)d_in[1];
    const float* aqual = (const float*)d_in[2];
    // d_in[3] = inactive_pc: unused by the reference
    const float* iroot = (const float*)d_in[4];
    const float* iqual = (const float*)d_in[5];
    const float* hpc   = (const float*)d_in[6];
    const float* hroot = (const float*)d_in[7];
    const float* hqual = (const float*)d_in[8];
    const int*   pco   = (n_in > 9) ? (const int*)d_in[9] : nullptr;

    static bool attr_done = false;
    if (!attr_done) {
        cudaFuncSetAttribute(main_kernel, cudaFuncAttributeMaxDynamicSharedMemorySize,
                             SM_FLOATS * 4);
        attr_done = true;
    }

    prep_kernel<<<KK * BB, 256>>>(apc, aroot, aqual, iroot, iqual);
    d_kernel<<<dim3(TT + 1, BB), 224>>>(hpc, hroot, hqual, pco);
    main_kernel<<<dim3(32, 8, BB), 256, SM_FLOATS * 4>>>((float*)d_out);
}